// round 11
// baseline (speedup 1.0000x reference)
#include <cuda_runtime.h>

#define B 8
#define C 256
#define NN 9216
#define KK 32

typedef unsigned long long ull;

// ---------------- f32x2 packed-FMA helpers (Blackwell FFMA2) ----------------
__device__ __forceinline__ ull pack2(float lo, float hi) {
    ull r;
    asm("mov.b64 %0, {%1, %2};" : "=l"(r) : "f"(lo), "f"(hi));
    return r;
}
__device__ __forceinline__ ull pack2s(float v) { return pack2(v, v); }
__device__ __forceinline__ void ffma2(ull& acc, ull a, ull b) {
    asm("fma.rn.f32x2 %0, %1, %2, %0;" : "+l"(acc) : "l"(a), "l"(b));
}
__device__ __forceinline__ float2 unpack2(ull v) {
    float2 r;
    asm("mov.b64 {%0, %1}, %2;" : "=f"(r.x), "=f"(r.y) : "l"(v));
    return r;
}

// ---------------- scratch (device globals; no allocation allowed) ----------
__device__ float g_cw[2 * C * KK];            // [c][0..31]=inv_s2, [c][32..63]=2*a*inv_s2
__device__ float g_sigma[KK * C];
__device__ float g_t3[KK];
__device__ float g_assign[B * KK * NN];       // 9.4 MB
__device__ float g_asum[B * KK];
__device__ float g_agg[B * KK * C];
__device__ float g_gram[B * KK * KK];
__device__ float g_nodes[B * KK * C];
__device__ float g_y1[B * C * KK];
__device__ float g_sc1[C], g_sh1[C];
__device__ float g_xf2[B * C * KK];
__device__ float g_xf3[B * C * KK];
__device__ float g_M[B * C * KK];
__device__ float g_s1[C], g_s2[C];
__device__ float g_sc2[C], g_sh2[C];

// ---------------- zero scratch accumulators --------------------------------
__global__ void zero_kernel() {
    int i = blockIdx.x * blockDim.x + threadIdx.x;   // 65536 threads
    if (i < B * KK * C) g_agg[i] = 0.f;
    if (i < B * KK * KK) g_gram[i] = 0.f;
    if (i < B * KK) g_asum[i] = 0.f;
    if (i < C) { g_s1[i] = 0.f; g_s2[i] = 0.f; }
}

// ---------------- prep: sigma, inv_s2, coef, t3 -----------------------------
__global__ void prep_kernel(const float* __restrict__ anchor,
                            const float* __restrict__ sigma_p) {
    int k = blockIdx.x, c = threadIdx.x;
    int idx = k * C + c;
    float sp = sigma_p[idx];
    float s = 1.f / (1.f + expf(-sp));
    float inv = 1.f / (s * s);
    float a = anchor[idx];
    g_sigma[idx] = s;
    g_cw[c * 64 + k] = inv;
    g_cw[c * 64 + 32 + k] = 2.f * a * inv;
    __shared__ float red[C];
    red[c] = a * a * inv;
    __syncthreads();
    for (int st = 128; st > 0; st >>= 1) {
        if (c < st) red[c] += red[c + st];
        __syncthreads();
    }
    if (c == 0) g_t3[k] = red[0];
}

// ---------------- assign: logits + softmax over K + asum --------------------
__global__ void __launch_bounds__(128) assign_kernel(const float* __restrict__ x) {
    extern __shared__ float sm[];
    float* s_cw = sm;              // 16384 floats
    float* s_t3 = sm + 16384;      // 32 floats
    const int tid = threadIdx.x;
    for (int i = tid; i < 4096; i += 128)
        ((float4*)s_cw)[i] = ((const float4*)g_cw)[i];
    if (tid < KK) s_t3[tid] = g_t3[tid];
    __syncthreads();

    const int b = blockIdx.x / 36;
    const int n0 = (blockIdx.x % 36) * 256;
    const int n1 = n0 + tid, n2 = n1 + 128;
    const float* xb = x + (size_t)b * C * NN;

    ull acc0[16], acc1[16];
#pragma unroll
    for (int p = 0; p < 16; p++) { acc0[p] = 0ull; acc1[p] = 0ull; }

    float nx0[8], nx1[8];
#pragma unroll
    for (int j = 0; j < 8; j++) {
        nx0[j] = __ldg(xb + j * NN + n1);
        nx1[j] = __ldg(xb + j * NN + n2);
    }

    for (int c0 = 0; c0 < C; c0 += 8) {
        float cx0[8], cx1[8];
#pragma unroll
        for (int j = 0; j < 8; j++) { cx0[j] = nx0[j]; cx1[j] = nx1[j]; }
        if (c0 + 8 < C) {
#pragma unroll
            for (int j = 0; j < 8; j++) {
                nx0[j] = __ldg(xb + (c0 + 8 + j) * NN + n1);
                nx1[j] = __ldg(xb + (c0 + 8 + j) * NN + n2);
            }
        }
#pragma unroll
        for (int j = 0; j < 8; j++) {
            const int c = c0 + j;
            float xv0 = cx0[j], xv1 = cx1[j];
            ull xx0 = pack2s(xv0 * xv0), mx0 = pack2s(-xv0);
            ull xx1 = pack2s(xv1 * xv1), mx1 = pack2s(-xv1);
            const ulonglong2* w = (const ulonglong2*)(s_cw + c * 64);
#pragma unroll
            for (int q = 0; q < 8; q++) {
                ulonglong2 wa = w[q];
                ulonglong2 wb = w[q + 8];
                ffma2(acc0[2 * q],     xx0, wa.x);
                ffma2(acc0[2 * q + 1], xx0, wa.y);
                ffma2(acc0[2 * q],     mx0, wb.x);
                ffma2(acc0[2 * q + 1], mx0, wb.y);
                ffma2(acc1[2 * q],     xx1, wa.x);
                ffma2(acc1[2 * q + 1], xx1, wa.y);
                ffma2(acc1[2 * q],     mx1, wb.x);
                ffma2(acc1[2 * q + 1], mx1, wb.y);
            }
        }
    }

    float l0[KK], l1[KK];
#pragma unroll
    for (int p = 0; p < 16; p++) {
        float2 v0 = unpack2(acc0[p]);
        float2 v1 = unpack2(acc1[p]);
        l0[2 * p] = v0.x; l0[2 * p + 1] = v0.y;
        l1[2 * p] = v1.x; l1[2 * p + 1] = v1.y;
    }
    float m0 = -1e30f, m1 = -1e30f;
#pragma unroll
    for (int k = 0; k < KK; k++) {
        l0[k] = -0.5f * (l0[k] + s_t3[k]);
        l1[k] = -0.5f * (l1[k] + s_t3[k]);
        m0 = fmaxf(m0, l0[k]);
        m1 = fmaxf(m1, l1[k]);
    }
    float sum0 = 0.f, sum1 = 0.f;
#pragma unroll
    for (int k = 0; k < KK; k++) {
        l0[k] = __expf(l0[k] - m0); sum0 += l0[k];
        l1[k] = __expf(l1[k] - m1); sum1 += l1[k];
    }
    float r0 = 1.f / sum0, r1 = 1.f / sum1;
    float* ab = g_assign + (size_t)b * KK * NN;
#pragma unroll
    for (int k = 0; k < KK; k++) {
        float p0 = l0[k] * r0, p1 = l1[k] * r1;
        ab[k * NN + n1] = p0;
        ab[k * NN + n2] = p1;
        l0[k] = p0 + p1;
    }
#pragma unroll
    for (int k = 0; k < KK; k++) {
        float v = l0[k];
        for (int o = 16; o; o >>= 1) v += __shfl_xor_sync(0xffffffffu, v, o);
        if ((tid & 31) == 0) atomicAdd(&g_asum[b * KK + k], v);
    }
}

// ---------------- agg[b,k,c] = sum_n assign*x  (R6 inner loop, 2x grid) ----
// grid (72 nchunks, B), 128 threads, full C per block, n-chunk 128.
// Thread: 8k x 8c, FFMA2 packed over c.
__global__ void __launch_bounds__(128) agg_kernel(const float* __restrict__ x) {
    __shared__ float s_x[32][260];   // [n][c], 1040B row stride
    __shared__ float s_a[32][36];    // [n][k], 144B row stride
    const int b = blockIdx.y;
    const int nbase = blockIdx.x * 128;
    const int tid = threadIdx.x;
    const int tx = tid & 31, ty = tid >> 5;
    const int k0 = ty * 8;
    const float* ab = g_assign + (size_t)b * KK * NN;
    const float* xb = x + (size_t)b * C * NN;

    ull acc[8][4];
#pragma unroll
    for (int i = 0; i < 8; i++)
#pragma unroll
        for (int j = 0; j < 4; j++) acc[i][j] = 0ull;

    for (int t = 0; t < 4; t++) {
        const int nb = nbase + t * 32;
        // load a tile 32k x 32n -> s_a[n][k]
        {
            int k = tid >> 2, n8 = (tid & 3) * 8;
            float4 a0 = *(const float4*)&ab[k * NN + nb + n8];
            float4 a1 = *(const float4*)&ab[k * NN + nb + n8 + 4];
            s_a[n8 + 0][k] = a0.x; s_a[n8 + 1][k] = a0.y;
            s_a[n8 + 2][k] = a0.z; s_a[n8 + 3][k] = a0.w;
            s_a[n8 + 4][k] = a1.x; s_a[n8 + 5][k] = a1.y;
            s_a[n8 + 6][k] = a1.z; s_a[n8 + 7][k] = a1.w;
        }
        // load x tile 256c x 32n -> s_x[n][c]
        {
            int cr = tid >> 3, n4 = (tid & 7) * 4;
#pragma unroll
            for (int p = 0; p < 16; p++) {
                int c = p * 16 + cr;
                float4 xv = *(const float4*)&xb[(size_t)c * NN + nb + n4];
                s_x[n4 + 0][c] = xv.x; s_x[n4 + 1][c] = xv.y;
                s_x[n4 + 2][c] = xv.z; s_x[n4 + 3][c] = xv.w;
            }
        }
        __syncthreads();
#pragma unroll 8
        for (int n = 0; n < 32; n++) {
            float4 alo = *(const float4*)&s_a[n][k0];
            float4 ahi = *(const float4*)&s_a[n][k0 + 4];
            ulonglong2 xlo = *(const ulonglong2*)&s_x[n][tx * 4];
            ulonglong2 xhi = *(const ulonglong2*)&s_x[n][128 + tx * 4];
            ull ap[8];
            ap[0] = pack2s(alo.x); ap[1] = pack2s(alo.y);
            ap[2] = pack2s(alo.z); ap[3] = pack2s(alo.w);
            ap[4] = pack2s(ahi.x); ap[5] = pack2s(ahi.y);
            ap[6] = pack2s(ahi.z); ap[7] = pack2s(ahi.w);
#pragma unroll
            for (int kk = 0; kk < 8; kk++) {
                ffma2(acc[kk][0], ap[kk], xlo.x);
                ffma2(acc[kk][1], ap[kk], xlo.y);
                ffma2(acc[kk][2], ap[kk], xhi.x);
                ffma2(acc[kk][3], ap[kk], xhi.y);
            }
        }
        __syncthreads();
    }
#pragma unroll
    for (int kk = 0; kk < 8; kk++) {
#pragma unroll
        for (int p = 0; p < 4; p++) {
            float2 v = unpack2(acc[kk][p]);
            int c = ((p >> 1) ? 128 : 0) + tx * 4 + (p & 1) * 2;
            atomicAdd(&g_agg[(b * KK + k0 + kk) * C + c], v.x);
            atomicAdd(&g_agg[(b * KK + k0 + kk) * C + c + 1], v.y);
        }
    }
}

// ---------------- gram[b,k,k'] = sum_n a_k a_k' ----------------------------
// grid (18, B), 256 threads, tile n=64. Row stride 68 floats (16B aligned).
__global__ void __launch_bounds__(256) gram_kernel() {
    __shared__ float s_a[32][68];
    const int b = blockIdx.y;
    const int nbase = blockIdx.x * 512;
    const int tid = threadIdx.x;
    const int i = tid >> 3, j4 = (tid & 7) * 4;
    const float* ab = g_assign + (size_t)b * KK * NN;
    float a0 = 0.f, a1 = 0.f, a2 = 0.f, a3 = 0.f;
    for (int t = 0; t < 8; t++) {
        int nb = nbase + t * 64;
        int k = tid >> 3, nn = (tid & 7) * 8;
        *(float4*)&s_a[k][nn]     = *(const float4*)&ab[k * NN + nb + nn];
        *(float4*)&s_a[k][nn + 4] = *(const float4*)&ab[k * NN + nb + nn + 4];
        __syncthreads();
#pragma unroll 8
        for (int n = 0; n < 64; n++) {
            float xi = s_a[i][n];
            a0 = fmaf(xi, s_a[j4 + 0][n], a0);
            a1 = fmaf(xi, s_a[j4 + 1][n], a1);
            a2 = fmaf(xi, s_a[j4 + 2][n], a2);
            a3 = fmaf(xi, s_a[j4 + 3][n], a3);
        }
        __syncthreads();
    }
    atomicAdd(&g_gram[(b * KK + i) * KK + j4 + 0], a0);
    atomicAdd(&g_gram[(b * KK + i) * KK + j4 + 1], a1);
    atomicAdd(&g_gram[(b * KK + i) * KK + j4 + 2], a2);
    atomicAdd(&g_gram[(b * KK + i) * KK + j4 + 3], a3);
}

// ---------------- nodes + per-node L2 norm + flat norm ----------------------
__global__ void __launch_bounds__(256) nodes_kernel(const float* __restrict__ anchor) {
    __shared__ float s_nd[KK][C];
    __shared__ float s_rk[KK];
    __shared__ float s_red[256];
    __shared__ float s_fr;
    int b = blockIdx.x, t = threadIdx.x;
#pragma unroll 4
    for (int k = 0; k < KK; k++) {
        float ask = g_asum[b * KK + k];
        float v = (g_agg[(b * KK + k) * C + t] - ask * anchor[k * C + t]) /
                  (g_sigma[k * C + t] * (ask + 1e-9f));
        s_nd[k][t] = v;
    }
    __syncthreads();
    int w = t >> 5, lane = t & 31;
    for (int kk = 0; kk < 4; kk++) {
        int k = w + kk * 8;
        float s = 0.f;
        for (int j = 0; j < 8; j++) { float v = s_nd[k][lane + 32 * j]; s = fmaf(v, v, s); }
        for (int o = 16; o; o >>= 1) s += __shfl_xor_sync(0xffffffffu, s, o);
        if (lane == 0) s_rk[k] = 1.f / fmaxf(sqrtf(s), 1e-12f);
    }
    __syncthreads();
    float fs = 0.f;
#pragma unroll 4
    for (int k = 0; k < KK; k++) {
        float v = s_nd[k][t] * s_rk[k];
        s_nd[k][t] = v;
        fs = fmaf(v, v, fs);
    }
    s_red[t] = fs;
    __syncthreads();
    for (int st = 128; st > 0; st >>= 1) {
        if (t < st) s_red[t] += s_red[t + st];
        __syncthreads();
    }
    if (t == 0) s_fr = 1.f / fmaxf(sqrtf(s_red[0]), 1e-12f);
    __syncthreads();
    float fr = s_fr;
#pragma unroll 4
    for (int k = 0; k < KK; k++)
        g_nodes[b * 8192 + k * C + t] = s_nd[k][t] * fr;
}

// ---------------- generic [C,C] x [C,K] conv: mode 0: nodes->y1, 1: xf3->M --
__global__ void __launch_bounds__(256) conv_kernel(const float* __restrict__ w, int mode) {
    __shared__ float s_in[C][KK];
    int b = blockIdx.y;
    int o0 = blockIdx.x * 32;
    int tid = threadIdx.x;
    const float* in = (mode == 0) ? g_nodes : g_xf3;
    float* out = (mode == 0) ? g_y1 : g_M;
    for (int i = tid; i < 2048; i += 256)
        ((float4*)s_in)[i] = ((const float4*)(in + b * 8192))[i];
    __syncthreads();
    int o = o0 + (tid >> 3), kq = tid & 7;
    const float* wr = w + o * C;
    float4 acc = {0.f, 0.f, 0.f, 0.f};
#pragma unroll 4
    for (int c = 0; c < C; c++) {
        float wv = __ldg(wr + c);
        float4 iv = *(const float4*)&s_in[c][kq * 4];
        acc.x = fmaf(wv, iv.x, acc.x);
        acc.y = fmaf(wv, iv.y, acc.y);
        acc.z = fmaf(wv, iv.z, acc.z);
        acc.w = fmaf(wv, iv.w, acc.w);
    }
    *(float4*)(out + b * 8192 + o * 32 + kq * 4) = acc;
}

// ---------------- BN1 stats -------------------------------------------------
__global__ void bn1_stats_kernel(const float* __restrict__ g, const float* __restrict__ beta) {
    int o = threadIdx.x;
    double s = 0.0, s2 = 0.0;
    for (int b = 0; b < B; b++) {
        const float* p = g_y1 + b * 8192 + o * 32;
        for (int k = 0; k < KK; k++) { double v = p[k]; s += v; s2 += v * v; }
    }
    double mean = s / 256.0;
    double var = s2 / 256.0 - mean * mean;
    if (var < 0.0) var = 0.0;
    float sc = (float)((double)g[o] / sqrt(var + 1e-5));
    g_sc1[o] = sc;
    g_sh1[o] = beta[o] - (float)mean * sc;
}

// ---------------- GCN layer, parallel over (d-tile, b) ----------------------
__global__ void __launch_bounds__(256) gcn_kernel(const float* __restrict__ w, int mode) {
    __shared__ float s_xf[C][KK];        // 32 KB
    __shared__ float s_adj[KK][KK + 1];
    __shared__ float s_sup[KK][KK + 1];
    const int b = blockIdx.y, d0 = blockIdx.x * 32;
    const int tid = threadIdx.x;
    const float* in = (mode == 0) ? g_y1 : g_xf2;
    float* out = (mode == 0) ? g_xf2 : g_xf3;

    for (int i = tid; i < 8192; i += 256) {
        float v = in[b * 8192 + i];
        if (mode == 0) { int c = i >> 5; v = fmaxf(fmaf(v, g_sc1[c], g_sh1[c]), 0.f); }
        ((float*)s_xf)[i] = v;
    }
    __syncthreads();
    {
        int i = tid >> 3, j4 = (tid & 7) * 4;
        float a0 = 0.f, a1 = 0.f, a2 = 0.f, a3 = 0.f;
#pragma unroll 4
        for (int c = 0; c < C; c++) {
            float xi = s_xf[c][i];
            float4 xj = *(const float4*)&s_xf[c][j4];
            a0 = fmaf(xi, xj.x, a0);
            a1 = fmaf(xi, xj.y, a1);
            a2 = fmaf(xi, xj.z, a2);
            a3 = fmaf(xi, xj.w, a3);
        }
        s_adj[i][j4 + 0] = a0; s_adj[i][j4 + 1] = a1;
        s_adj[i][j4 + 2] = a2; s_adj[i][j4 + 3] = a3;
    }
    __syncthreads();
    if (tid < KK) {
        float mx = -1e30f;
        for (int j = 0; j < KK; j++) mx = fmaxf(mx, s_adj[tid][j]);
        float sum = 0.f;
        for (int j = 0; j < KK; j++) { float e = __expf(s_adj[tid][j] - mx); s_adj[tid][j] = e; sum += e; }
        float r = 1.f / sum;
        for (int j = 0; j < KK; j++) s_adj[tid][j] *= r;
    }
    __syncthreads();
    const int d_local = tid & 31, ig = tid >> 5;
    {
        float acc[4] = {0.f, 0.f, 0.f, 0.f};
#pragma unroll 4
        for (int c = 0; c < C; c++) {
            float wv = __ldg(&w[c * C + d0 + d_local]);
            float4 x4 = *(const float4*)&s_xf[c][ig * 4];
            acc[0] = fmaf(wv, x4.x, acc[0]);
            acc[1] = fmaf(wv, x4.y, acc[1]);
            acc[2] = fmaf(wv, x4.z, acc[2]);
            acc[3] = fmaf(wv, x4.w, acc[3]);
        }
#pragma unroll
        for (int j = 0; j < 4; j++) s_sup[ig * 4 + j][d_local] = acc[j];
    }
    __syncthreads();
    {
#pragma unroll
        for (int jj = 0; jj < 4; jj++) {
            int i = ig * 4 + jj;
            float o = 0.f;
#pragma unroll
            for (int j = 0; j < KK; j++) o = fmaf(s_adj[i][j], s_sup[j][d_local], o);
            if (mode == 1) o = fmaxf(o, 0.f);
            out[b * 8192 + (d0 + d_local) * 32 + i] = o;
        }
    }
}

// ---------------- BN2 analytic stats ----------------------------------------
__global__ void __launch_bounds__(256) bn2_partial_kernel() {
    __shared__ float s_g[KK][KK];
    __shared__ float s_as[KK];
    int b = blockIdx.x, o = threadIdx.x;
    for (int i = o; i < 1024; i += 256) ((float*)s_g)[i] = g_gram[b * 1024 + i];
    if (o < KK) s_as[o] = g_asum[b * KK + o];
    __syncthreads();
    float m[KK];
#pragma unroll
    for (int k = 0; k < KK; k++) m[k] = g_M[b * 8192 + o * 32 + k];
    float sm = 0.f;
#pragma unroll
    for (int k = 0; k < KK; k++) sm = fmaf(m[k], s_as[k], sm);
    float sq = 0.f;
    for (int k = 0; k < KK; k++) {
        float t = 0.f;
#pragma unroll
        for (int k2 = 0; k2 < KK; k2++) t = fmaf(m[k2], s_g[k][k2], t);
        sq = fmaf(m[k], t, sq);
    }
    atomicAdd(&g_s1[o], sm);
    atomicAdd(&g_s2[o], sq);
}

__global__ void bn2_final_kernel(const float* __restrict__ g, const float* __restrict__ beta) {
    int o = threadIdx.x;
    double inv = 1.0 / ((double)B * NN);
    double mean = (double)g_s1[o] * inv;
    double var = (double)g_s2[o] * inv - mean * mean;
    if (var < 0.0) var = 0.0;
    float sc = (float)((double)g[o] / sqrt(var + 1e-5));
    g_sc2[o] = sc;
    g_sh2[o] = (float)((double)beta[o] - mean * sc);
}

// ---------------- final: out = x + relu(bn2(M @ assign)) -------------------
__global__ void __launch_bounds__(256) final_kernel(const float* __restrict__ x,
                                                    float* __restrict__ out) {
    __shared__ float s_Mt[KK][68];
    __shared__ float s_as[KK][68];
    int n0 = blockIdx.x * 64, c0 = blockIdx.y * 64, b = blockIdx.z;
    int tid = threadIdx.x;
    for (int i = tid; i < 2048; i += 256) {
        int r = i >> 5, k = i & 31;
        s_Mt[k][r] = g_M[b * 8192 + (c0 + r) * 32 + k];
    }
    const float* ab = g_assign + (size_t)b * KK * NN;
    for (int i = tid; i < 2048; i += 256) {
        int k = i >> 6, col = i & 63;
        s_as[k][col] = ab[k * NN + n0 + col];
    }
    __syncthreads();
    int ty = tid >> 4, tx = tid & 15;
    ull acc[4][2];
#pragma unroll
    for (int i = 0; i < 4; i++) { acc[i][0] = 0ull; acc[i][1] = 0ull; }
#pragma unroll
    for (int k = 0; k < KK; k++) {
        float4 a = *(const float4*)&s_Mt[k][ty * 4];
        ulonglong2 bp = *(const ulonglong2*)&s_as[k][tx * 4];
        ull a0 = pack2s(a.x), a1 = pack2s(a.y), a2 = pack2s(a.z), a3 = pack2s(a.w);
        ffma2(acc[0][0], a0, bp.x); ffma2(acc[0][1], a0, bp.y);
        ffma2(acc[1][0], a1, bp.x); ffma2(acc[1][1], a1, bp.y);
        ffma2(acc[2][0], a2, bp.x); ffma2(acc[2][1], a2, bp.y);
        ffma2(acc[3][0], a3, bp.x); ffma2(acc[3][1], a3, bp.y);
    }
    size_t base = (size_t)b * C * NN;
#pragma unroll
    for (int i = 0; i < 4; i++) {
        int c = c0 + ty * 4 + i;
        float sc = g_sc2[c], sh = g_sh2[c];
        size_t idx = base + (size_t)c * NN + n0 + tx * 4;
        float2 v0 = unpack2(acc[i][0]);
        float2 v1 = unpack2(acc[i][1]);
        float4 xv = *(const float4*)&x[idx];
        float4 r;
        r.x = xv.x + fmaxf(fmaf(v0.x, sc, sh), 0.f);
        r.y = xv.y + fmaxf(fmaf(v0.y, sc, sh), 0.f);
        r.z = xv.z + fmaxf(fmaf(v1.x, sc, sh), 0.f);
        r.w = xv.w + fmaxf(fmaf(v1.y, sc, sh), 0.f);
        *(float4*)&out[idx] = r;
    }
}

// ---------------------------------------------------------------------------
extern "C" void kernel_launch(void* const* d_in, const int* in_sizes, int n_in,
                              void* d_out, int out_size) {
    const float* x       = (const float*)d_in[0];
    const float* anchor  = (const float*)d_in[1];
    const float* sigma_p = (const float*)d_in[2];
    const float* conv1_w = (const float*)d_in[3];
    const float* bn1_g   = (const float*)d_in[4];
    const float* bn1_b   = (const float*)d_in[5];
    const float* gcn_w1  = (const float*)d_in[6];
    const float* gcn_w2  = (const float*)d_in[7];
    const float* conv2_w = (const float*)d_in[8];
    const float* bn2_g   = (const float*)d_in[9];
    const float* bn2_b   = (const float*)d_in[10];
    float* out = (float*)d_out;

    cudaFuncSetAttribute(assign_kernel, cudaFuncAttributeMaxDynamicSharedMemorySize,
                         (16384 + 32) * (int)sizeof(float));

    zero_kernel<<<256, 256>>>();
    prep_kernel<<<KK, C>>>(anchor, sigma_p);
    assign_kernel<<<288, 128, (16384 + 32) * sizeof(float)>>>(x);
    agg_kernel<<<dim3(72, B), 128>>>(x);
    gram_kernel<<<dim3(18, B), 256>>>();
    nodes_kernel<<<B, 256>>>(anchor);
    conv_kernel<<<dim3(8, B), 256>>>(conv1_w, 0);
    bn1_stats_kernel<<<1, C>>>(bn1_g, bn1_b);
    gcn_kernel<<<dim3(8, B), 256>>>(gcn_w1, 0);
    gcn_kernel<<<dim3(8, B), 256>>>(gcn_w2, 1);
    conv_kernel<<<dim3(8, B), 256>>>(conv2_w, 1);
    bn2_partial_kernel<<<B, 256>>>();
    bn2_final_kernel<<<1, C>>>(bn2_g, bn2_b);
    final_kernel<<<dim3(NN / 64, C / 64, B), 256>>>(x, out);
}

// round 15
// speedup vs baseline: 1.1435x; 1.1435x over previous
#include <cuda_runtime.h>

#define B 8
#define C 256
#define NN 9216
#define KK 32

typedef unsigned long long ull;

// ---------------- f32x2 packed-FMA helpers (Blackwell FFMA2) ----------------
__device__ __forceinline__ ull pack2(float lo, float hi) {
    ull r;
    asm("mov.b64 %0, {%1, %2};" : "=l"(r) : "f"(lo), "f"(hi));
    return r;
}
__device__ __forceinline__ ull pack2s(float v) { return pack2(v, v); }
__device__ __forceinline__ void ffma2(ull& acc, ull a, ull b) {
    asm("fma.rn.f32x2 %0, %1, %2, %0;" : "+l"(acc) : "l"(a), "l"(b));
}
__device__ __forceinline__ float2 unpack2(ull v) {
    float2 r;
    asm("mov.b64 {%0, %1}, %2;" : "=f"(r.x), "=f"(r.y) : "l"(v));
    return r;
}

// ---------------- scratch (device globals; no allocation allowed) ----------
__device__ float g_cw[2 * C * KK];
__device__ float g_sigma[KK * C];
__device__ float g_t3[KK];
__device__ float g_assign[B * KK * NN];       // 9.4 MB
__device__ float g_asum[B * KK];
__device__ float g_agg[B * KK * C];
__device__ float g_gram[B * KK * KK];
__device__ float g_nodes[B * KK * C];
__device__ float g_y1[B * C * KK];
__device__ float g_sc1[C], g_sh1[C];
__device__ float g_xf2[B * C * KK];
__device__ float g_xf3[B * C * KK];
__device__ float g_M[B * C * KK];
__device__ float g_s1[C], g_s2[C];
__device__ float g_sc2[C], g_sh2[C];

// ---------------- prep: sigma, inv_s2, coef, t3  (+ fused zeroing) ----------
__global__ void prep_kernel(const float* __restrict__ anchor,
                            const float* __restrict__ sigma_p) {
    int k = blockIdx.x, c = threadIdx.x;
    int gid = k * C + c;                       // 0..8191
    // fused zeroing of accumulators (8192 threads total)
#pragma unroll
    for (int i = 0; i < 8; i++) g_agg[gid + i * 8192] = 0.f;
    g_gram[gid] = 0.f;                          // exactly 8192
    if (gid < B * KK) g_asum[gid] = 0.f;
    if (gid < C) { g_s1[gid] = 0.f; g_s2[gid] = 0.f; }

    int idx = gid;
    float sp = sigma_p[idx];
    float s = 1.f / (1.f + expf(-sp));
    float inv = 1.f / (s * s);
    float a = anchor[idx];
    g_sigma[idx] = s;
    g_cw[c * 64 + k] = inv;
    g_cw[c * 64 + 32 + k] = 2.f * a * inv;
    __shared__ float red[C];
    red[c] = a * a * inv;
    __syncthreads();
    for (int st = 128; st > 0; st >>= 1) {
        if (c < st) red[c] += red[c + st];
        __syncthreads();
    }
    if (c == 0) g_t3[k] = red[0];
}

// ---------------- assign: logits + softmax over K + asum --------------------
__global__ void __launch_bounds__(128) assign_kernel(const float* __restrict__ x) {
    extern __shared__ float sm[];
    float* s_cw = sm;
    float* s_t3 = sm + 16384;
    const int tid = threadIdx.x;
    for (int i = tid; i < 4096; i += 128)
        ((float4*)s_cw)[i] = ((const float4*)g_cw)[i];
    if (tid < KK) s_t3[tid] = g_t3[tid];
    __syncthreads();

    const int b = blockIdx.x / 36;
    const int n0 = (blockIdx.x % 36) * 256;
    const int n1 = n0 + tid, n2 = n1 + 128;
    const float* xb = x + (size_t)b * C * NN;

    ull acc0[16], acc1[16];
#pragma unroll
    for (int p = 0; p < 16; p++) { acc0[p] = 0ull; acc1[p] = 0ull; }

    float nx0[8], nx1[8];
#pragma unroll
    for (int j = 0; j < 8; j++) {
        nx0[j] = __ldg(xb + j * NN + n1);
        nx1[j] = __ldg(xb + j * NN + n2);
    }

    for (int c0 = 0; c0 < C; c0 += 8) {
        float cx0[8], cx1[8];
#pragma unroll
        for (int j = 0; j < 8; j++) { cx0[j] = nx0[j]; cx1[j] = nx1[j]; }
        if (c0 + 8 < C) {
#pragma unroll
            for (int j = 0; j < 8; j++) {
                nx0[j] = __ldg(xb + (c0 + 8 + j) * NN + n1);
                nx1[j] = __ldg(xb + (c0 + 8 + j) * NN + n2);
            }
        }
#pragma unroll
        for (int j = 0; j < 8; j++) {
            const int c = c0 + j;
            float xv0 = cx0[j], xv1 = cx1[j];
            ull xx0 = pack2s(xv0 * xv0), mx0 = pack2s(-xv0);
            ull xx1 = pack2s(xv1 * xv1), mx1 = pack2s(-xv1);
            const ulonglong2* w = (const ulonglong2*)(s_cw + c * 64);
#pragma unroll
            for (int q = 0; q < 8; q++) {
                ulonglong2 wa = w[q];
                ulonglong2 wb = w[q + 8];
                ffma2(acc0[2 * q],     xx0, wa.x);
                ffma2(acc0[2 * q + 1], xx0, wa.y);
                ffma2(acc0[2 * q],     mx0, wb.x);
                ffma2(acc0[2 * q + 1], mx0, wb.y);
                ffma2(acc1[2 * q],     xx1, wa.x);
                ffma2(acc1[2 * q + 1], xx1, wa.y);
                ffma2(acc1[2 * q],     mx1, wb.x);
                ffma2(acc1[2 * q + 1], mx1, wb.y);
            }
        }
    }

    float l0[KK], l1[KK];
#pragma unroll
    for (int p = 0; p < 16; p++) {
        float2 v0 = unpack2(acc0[p]);
        float2 v1 = unpack2(acc1[p]);
        l0[2 * p] = v0.x; l0[2 * p + 1] = v0.y;
        l1[2 * p] = v1.x; l1[2 * p + 1] = v1.y;
    }
    float m0 = -1e30f, m1 = -1e30f;
#pragma unroll
    for (int k = 0; k < KK; k++) {
        l0[k] = -0.5f * (l0[k] + s_t3[k]);
        l1[k] = -0.5f * (l1[k] + s_t3[k]);
        m0 = fmaxf(m0, l0[k]);
        m1 = fmaxf(m1, l1[k]);
    }
    float sum0 = 0.f, sum1 = 0.f;
#pragma unroll
    for (int k = 0; k < KK; k++) {
        l0[k] = __expf(l0[k] - m0); sum0 += l0[k];
        l1[k] = __expf(l1[k] - m1); sum1 += l1[k];
    }
    float r0 = 1.f / sum0, r1 = 1.f / sum1;
    float* ab = g_assign + (size_t)b * KK * NN;
#pragma unroll
    for (int k = 0; k < KK; k++) {
        float p0 = l0[k] * r0, p1 = l1[k] * r1;
        ab[k * NN + n1] = p0;
        ab[k * NN + n2] = p1;
        l0[k] = p0 + p1;
    }
#pragma unroll
    for (int k = 0; k < KK; k++) {
        float v = l0[k];
        for (int o = 16; o; o >>= 1) v += __shfl_xor_sync(0xffffffffu, v, o);
        if ((tid & 31) == 0) atomicAdd(&g_asum[b * KK + k], v);
    }
}

// ---------------- agg[b,k,c] = sum_n assign*x  (R6 inner, 2x grid) ----------
__global__ void __launch_bounds__(128) agg_kernel(const float* __restrict__ x) {
    __shared__ float s_x[32][260];
    __shared__ float s_a[32][36];
    const int b = blockIdx.y;
    const int nbase = blockIdx.x * 128;
    const int tid = threadIdx.x;
    const int tx = tid & 31, ty = tid >> 5;
    const int k0 = ty * 8;
    const float* ab = g_assign + (size_t)b * KK * NN;
    const float* xb = x + (size_t)b * C * NN;

    ull acc[8][4];
#pragma unroll
    for (int i = 0; i < 8; i++)
#pragma unroll
        for (int j = 0; j < 4; j++) acc[i][j] = 0ull;

    for (int t = 0; t < 4; t++) {
        const int nb = nbase + t * 32;
        {
            int k = tid >> 2, n8 = (tid & 3) * 8;
            float4 a0 = *(const float4*)&ab[k * NN + nb + n8];
            float4 a1 = *(const float4*)&ab[k * NN + nb + n8 + 4];
            s_a[n8 + 0][k] = a0.x; s_a[n8 + 1][k] = a0.y;
            s_a[n8 + 2][k] = a0.z; s_a[n8 + 3][k] = a0.w;
            s_a[n8 + 4][k] = a1.x; s_a[n8 + 5][k] = a1.y;
            s_a[n8 + 6][k] = a1.z; s_a[n8 + 7][k] = a1.w;
        }
        {
            int cr = tid >> 3, n4 = (tid & 7) * 4;
#pragma unroll
            for (int p = 0; p < 16; p++) {
                int c = p * 16 + cr;
                float4 xv = *(const float4*)&xb[(size_t)c * NN + nb + n4];
                s_x[n4 + 0][c] = xv.x; s_x[n4 + 1][c] = xv.y;
                s_x[n4 + 2][c] = xv.z; s_x[n4 + 3][c] = xv.w;
            }
        }
        __syncthreads();
#pragma unroll 8
        for (int n = 0; n < 32; n++) {
            float4 alo = *(const float4*)&s_a[n][k0];
            float4 ahi = *(const float4*)&s_a[n][k0 + 4];
            ulonglong2 xlo = *(const ulonglong2*)&s_x[n][tx * 4];
            ulonglong2 xhi = *(const ulonglong2*)&s_x[n][128 + tx * 4];
            ull ap[8];
            ap[0] = pack2s(alo.x); ap[1] = pack2s(alo.y);
            ap[2] = pack2s(alo.z); ap[3] = pack2s(alo.w);
            ap[4] = pack2s(ahi.x); ap[5] = pack2s(ahi.y);
            ap[6] = pack2s(ahi.z); ap[7] = pack2s(ahi.w);
#pragma unroll
            for (int kk = 0; kk < 8; kk++) {
                ffma2(acc[kk][0], ap[kk], xlo.x);
                ffma2(acc[kk][1], ap[kk], xlo.y);
                ffma2(acc[kk][2], ap[kk], xhi.x);
                ffma2(acc[kk][3], ap[kk], xhi.y);
            }
        }
        __syncthreads();
    }
#pragma unroll
    for (int kk = 0; kk < 8; kk++) {
#pragma unroll
        for (int p = 0; p < 4; p++) {
            float2 v = unpack2(acc[kk][p]);
            int c = ((p >> 1) ? 128 : 0) + tx * 4 + (p & 1) * 2;
            atomicAdd(&g_agg[(b * KK + k0 + kk) * C + c], v.x);
            atomicAdd(&g_agg[(b * KK + k0 + kk) * C + c + 1], v.y);
        }
    }
}

// ---------------- gram[b,k,k'] = sum_n a_k a_k' ----------------------------
__global__ void __launch_bounds__(256) gram_kernel() {
    __shared__ float s_a[32][68];
    const int b = blockIdx.y;
    const int nbase = blockIdx.x * 512;
    const int tid = threadIdx.x;
    const int i = tid >> 3, j4 = (tid & 7) * 4;
    const float* ab = g_assign + (size_t)b * KK * NN;
    float a0 = 0.f, a1 = 0.f, a2 = 0.f, a3 = 0.f;
    for (int t = 0; t < 8; t++) {
        int nb = nbase + t * 64;
        int k = tid >> 3, nn = (tid & 7) * 8;
        *(float4*)&s_a[k][nn]     = *(const float4*)&ab[k * NN + nb + nn];
        *(float4*)&s_a[k][nn + 4] = *(const float4*)&ab[k * NN + nb + nn + 4];
        __syncthreads();
#pragma unroll 8
        for (int n = 0; n < 64; n++) {
            float xi = s_a[i][n];
            a0 = fmaf(xi, s_a[j4 + 0][n], a0);
            a1 = fmaf(xi, s_a[j4 + 1][n], a1);
            a2 = fmaf(xi, s_a[j4 + 2][n], a2);
            a3 = fmaf(xi, s_a[j4 + 3][n], a3);
        }
        __syncthreads();
    }
    atomicAdd(&g_gram[(b * KK + i) * KK + j4 + 0], a0);
    atomicAdd(&g_gram[(b * KK + i) * KK + j4 + 1], a1);
    atomicAdd(&g_gram[(b * KK + i) * KK + j4 + 2], a2);
    atomicAdd(&g_gram[(b * KK + i) * KK + j4 + 3], a3);
}

// ---------------- nodes + per-node L2 norm + flat norm ----------------------
__global__ void __launch_bounds__(256) nodes_kernel(const float* __restrict__ anchor) {
    __shared__ float s_nd[KK][C];
    __shared__ float s_rk[KK];
    __shared__ float s_red[256];
    __shared__ float s_fr;
    int b = blockIdx.x, t = threadIdx.x;
#pragma unroll 4
    for (int k = 0; k < KK; k++) {
        float ask = g_asum[b * KK + k];
        float v = (g_agg[(b * KK + k) * C + t] - ask * anchor[k * C + t]) /
                  (g_sigma[k * C + t] * (ask + 1e-9f));
        s_nd[k][t] = v;
    }
    __syncthreads();
    int w = t >> 5, lane = t & 31;
    for (int kk = 0; kk < 4; kk++) {
        int k = w + kk * 8;
        float s = 0.f;
        for (int j = 0; j < 8; j++) { float v = s_nd[k][lane + 32 * j]; s = fmaf(v, v, s); }
        for (int o = 16; o; o >>= 1) s += __shfl_xor_sync(0xffffffffu, s, o);
        if (lane == 0) s_rk[k] = 1.f / fmaxf(sqrtf(s), 1e-12f);
    }
    __syncthreads();
    float fs = 0.f;
#pragma unroll 4
    for (int k = 0; k < KK; k++) {
        float v = s_nd[k][t] * s_rk[k];
        s_nd[k][t] = v;
        fs = fmaf(v, v, fs);
    }
    s_red[t] = fs;
    __syncthreads();
    for (int st = 128; st > 0; st >>= 1) {
        if (t < st) s_red[t] += s_red[t + st];
        __syncthreads();
    }
    if (t == 0) s_fr = 1.f / fmaxf(sqrtf(s_red[0]), 1e-12f);
    __syncthreads();
    float fr = s_fr;
#pragma unroll 4
    for (int k = 0; k < KK; k++)
        g_nodes[b * 8192 + k * C + t] = s_nd[k][t] * fr;
}

// ---------------- conv [C,C]x[C,K]: grid (16,B), 128 thr, FFMA2 -------------
__global__ void __launch_bounds__(128) conv_kernel(const float* __restrict__ w, int mode) {
    __shared__ float s_in[C * KK];
    int b = blockIdx.y;
    int o0 = blockIdx.x * 16;
    int tid = threadIdx.x;
    const float* in = (mode == 0) ? g_nodes : g_xf3;
    float* out = (mode == 0) ? g_y1 : g_M;
    for (int i = tid; i < 2048; i += 128)
        ((float4*)s_in)[i] = ((const float4*)(in + b * 8192))[i];
    __syncthreads();
    int o = o0 + (tid >> 3), kq = (tid & 7) * 4;
    const float* wr = w + o * C;
    ull acc0 = 0ull, acc1 = 0ull;
#pragma unroll 4
    for (int c = 0; c < C; c++) {
        ull wp = pack2s(__ldg(wr + c));
        ulonglong2 iv = *(const ulonglong2*)&s_in[c * 32 + kq];
        ffma2(acc0, wp, iv.x);
        ffma2(acc1, wp, iv.y);
    }
    float2 v0 = unpack2(acc0), v1 = unpack2(acc1);
    *(float4*)(out + b * 8192 + o * 32 + kq) = make_float4(v0.x, v0.y, v1.x, v1.y);
}

// ---------------- BN1 stats (parallel float partials) ----------------------
__global__ void bn1_stats_kernel(const float* __restrict__ g, const float* __restrict__ beta) {
    int o = threadIdx.x;
    float s0 = 0.f, s1 = 0.f, s2 = 0.f, s3 = 0.f;
    float q0 = 0.f, q1 = 0.f, q2 = 0.f, q3 = 0.f;
    for (int b = 0; b < B; b++) {
        const float4* p = (const float4*)(g_y1 + b * 8192 + o * 32);
#pragma unroll
        for (int j = 0; j < 8; j++) {
            float4 v = p[j];
            s0 += v.x; s1 += v.y; s2 += v.z; s3 += v.w;
            q0 = fmaf(v.x, v.x, q0); q1 = fmaf(v.y, v.y, q1);
            q2 = fmaf(v.z, v.z, q2); q3 = fmaf(v.w, v.w, q3);
        }
    }
    double s = (double)s0 + s1 + s2 + s3;
    double sq = (double)q0 + q1 + q2 + q3;
    double mean = s / 256.0;
    double var = sq / 256.0 - mean * mean;
    if (var < 0.0) var = 0.0;
    float sc = (float)((double)g[o] / sqrt(var + 1e-5));
    g_sc1[o] = sc;
    g_sh1[o] = beta[o] - (float)mean * sc;
}

// ---------------- GCN layer, parallel over (d-tile, b) ----------------------
__global__ void __launch_bounds__(256) gcn_kernel(const float* __restrict__ w, int mode) {
    __shared__ float s_xf[C][KK];
    __shared__ float s_adj[KK][KK + 1];
    __shared__ float s_sup[KK][KK + 1];
    const int b = blockIdx.y, d0 = blockIdx.x * 32;
    const int tid = threadIdx.x;
    const float* in = (mode == 0) ? g_y1 : g_xf2;
    float* out = (mode == 0) ? g_xf2 : g_xf3;

    for (int i = tid; i < 8192; i += 256) {
        float v = in[b * 8192 + i];
        if (mode == 0) { int c = i >> 5; v = fmaxf(fmaf(v, g_sc1[c], g_sh1[c]), 0.f); }
        ((float*)s_xf)[i] = v;
    }
    __syncthreads();
    {
        int i = tid >> 3, j4 = (tid & 7) * 4;
        float a0 = 0.f, a1 = 0.f, a2 = 0.f, a3 = 0.f;
#pragma unroll 4
        for (int c = 0; c < C; c++) {
            float xi = s_xf[c][i];
            float4 xj = *(const float4*)&s_xf[c][j4];
            a0 = fmaf(xi, xj.x, a0);
            a1 = fmaf(xi, xj.y, a1);
            a2 = fmaf(xi, xj.z, a2);
            a3 = fmaf(xi, xj.w, a3);
        }
        s_adj[i][j4 + 0] = a0; s_adj[i][j4 + 1] = a1;
        s_adj[i][j4 + 2] = a2; s_adj[i][j4 + 3] = a3;
    }
    __syncthreads();
    if (tid < KK) {
        float mx = -1e30f;
        for (int j = 0; j < KK; j++) mx = fmaxf(mx, s_adj[tid][j]);
        float sum = 0.f;
        for (int j = 0; j < KK; j++) { float e = __expf(s_adj[tid][j] - mx); s_adj[tid][j] = e; sum += e; }
        float r = 1.f / sum;
        for (int j = 0; j < KK; j++) s_adj[tid][j] *= r;
    }
    __syncthreads();
    const int d_local = tid & 31, ig = tid >> 5;
    {
        ull accA = 0ull, accB = 0ull;
#pragma unroll 4
        for (int c = 0; c < C; c++) {
            ull wp = pack2s(__ldg(&w[c * C + d0 + d_local]));
            ulonglong2 x2 = *(const ulonglong2*)&s_xf[c][ig * 4];
            ffma2(accA, wp, x2.x);
            ffma2(accB, wp, x2.y);
        }
        float2 vA = unpack2(accA), vB = unpack2(accB);
        s_sup[ig * 4 + 0][d_local] = vA.x;
        s_sup[ig * 4 + 1][d_local] = vA.y;
        s_sup[ig * 4 + 2][d_local] = vB.x;
        s_sup[ig * 4 + 3][d_local] = vB.y;
    }
    __syncthreads();
    {
#pragma unroll
        for (int jj = 0; jj < 4; jj++) {
            int i = ig * 4 + jj;
            float o = 0.f;
#pragma unroll
            for (int j = 0; j < KK; j++) o = fmaf(s_adj[i][j], s_sup[j][d_local], o);
            if (mode == 1) o = fmaxf(o, 0.f);
            out[b * 8192 + (d0 + d_local) * 32 + i] = o;
        }
    }
}

// ---------------- BN2 analytic stats ----------------------------------------
__global__ void __launch_bounds__(256) bn2_partial_kernel() {
    __shared__ float s_g[KK][KK];
    __shared__ float s_as[KK];
    int b = blockIdx.x, o = threadIdx.x;
    for (int i = o; i < 1024; i += 256) ((float*)s_g)[i] = g_gram[b * 1024 + i];
    if (o < KK) s_as[o] = g_asum[b * KK + o];
    __syncthreads();
    float m[KK];
#pragma unroll
    for (int k = 0; k < KK; k++) m[k] = g_M[b * 8192 + o * 32 + k];
    float sm = 0.f;
#pragma unroll
    for (int k = 0; k < KK; k++) sm = fmaf(m[k], s_as[k], sm);
    float sq = 0.f;
    for (int k = 0; k < KK; k++) {
        float t = 0.f;
#pragma unroll
        for (int k2 = 0; k2 < KK; k2++) t = fmaf(m[k2], s_g[k][k2], t);
        sq = fmaf(m[k], t, sq);
    }
    atomicAdd(&g_s1[o], sm);
    atomicAdd(&g_s2[o], sq);
}

__global__ void bn2_final_kernel(const float* __restrict__ g, const float* __restrict__ beta) {
    int o = threadIdx.x;
    double inv = 1.0 / ((double)B * NN);
    double mean = (double)g_s1[o] * inv;
    double var = (double)g_s2[o] * inv - mean * mean;
    if (var < 0.0) var = 0.0;
    float sc = (float)((double)g[o] / sqrt(var + 1e-5));
    g_sc2[o] = sc;
    g_sh2[o] = (float)((double)beta[o] - mean * sc);
}

// ---------------- final: out = x + relu(bn2(M @ assign)) -------------------
__global__ void __launch_bounds__(256) final_kernel(const float* __restrict__ x,
                                                    float* __restrict__ out) {
    __shared__ float s_Mt[KK][68];
    __shared__ float s_as[KK][68];
    int n0 = blockIdx.x * 64, c0 = blockIdx.y * 64, b = blockIdx.z;
    int tid = threadIdx.x;
    for (int i = tid; i < 2048; i += 256) {
        int r = i >> 5, k = i & 31;
        s_Mt[k][r] = g_M[b * 8192 + (c0 + r) * 32 + k];
    }
    const float* ab = g_assign + (size_t)b * KK * NN;
    for (int i = tid; i < 2048; i += 256) {
        int k = i >> 6, col = i & 63;
        s_as[k][col] = ab[k * NN + n0 + col];
    }
    __syncthreads();
    int ty = tid >> 4, tx = tid & 15;
    ull acc[4][2];
#pragma unroll
    for (int i = 0; i < 4; i++) { acc[i][0] = 0ull; acc[i][1] = 0ull; }
#pragma unroll
    for (int k = 0; k < KK; k++) {
        float4 a = *(const float4*)&s_Mt[k][ty * 4];
        ulonglong2 bp = *(const ulonglong2*)&s_as[k][tx * 4];
        ull a0 = pack2s(a.x), a1 = pack2s(a.y), a2 = pack2s(a.z), a3 = pack2s(a.w);
        ffma2(acc[0][0], a0, bp.x); ffma2(acc[0][1], a0, bp.y);
        ffma2(acc[1][0], a1, bp.x); ffma2(acc[1][1], a1, bp.y);
        ffma2(acc[2][0], a2, bp.x); ffma2(acc[2][1], a2, bp.y);
        ffma2(acc[3][0], a3, bp.x); ffma2(acc[3][1], a3, bp.y);
    }
    size_t base = (size_t)b * C * NN;
#pragma unroll
    for (int i = 0; i < 4; i++) {
        int c = c0 + ty * 4 + i;
        float sc = g_sc2[c], sh = g_sh2[c];
        size_t idx = base + (size_t)c * NN + n0 + tx * 4;
        float2 v0 = unpack2(acc[i][0]);
        float2 v1 = unpack2(acc[i][1]);
        float4 xv = *(const float4*)&x[idx];
        float4 r;
        r.x = xv.x + fmaxf(fmaf(v0.x, sc, sh), 0.f);
        r.y = xv.y + fmaxf(fmaf(v0.y, sc, sh), 0.f);
        r.z = xv.z + fmaxf(fmaf(v1.x, sc, sh), 0.f);
        r.w = xv.w + fmaxf(fmaf(v1.y, sc, sh), 0.f);
        *(float4*)&out[idx] = r;
    }
}

// ---------------------------------------------------------------------------
extern "C" void kernel_launch(void* const* d_in, const int* in_sizes, int n_in,
                              void* d_out, int out_size) {
    const float* x       = (const float*)d_in[0];
    const float* anchor  = (const float*)d_in[1];
    const float* sigma_p = (const float*)d_in[2];
    const float* conv1_w = (const float*)d_in[3];
    const float* bn1_g   = (const float*)d_in[4];
    const float* bn1_b   = (const float*)d_in[5];
    const float* gcn_w1  = (const float*)d_in[6];
    const float* gcn_w2  = (const float*)d_in[7];
    const float* conv2_w = (const float*)d_in[8];
    const float* bn2_g   = (const float*)d_in[9];
    const float* bn2_b   = (const float*)d_in[10];
    float* out = (float*)d_out;

    cudaFuncSetAttribute(assign_kernel, cudaFuncAttributeMaxDynamicSharedMemorySize,
                         (16384 + 32) * (int)sizeof(float));

    prep_kernel<<<KK, C>>>(anchor, sigma_p);
    assign_kernel<<<288, 128, (16384 + 32) * sizeof(float)>>>(x);
    agg_kernel<<<dim3(72, B), 128>>>(x);
    gram_kernel<<<dim3(18, B), 256>>>();
    nodes_kernel<<<B, 256>>>(anchor);
    conv_kernel<<<dim3(16, B), 128>>>(conv1_w, 0);
    bn1_stats_kernel<<<1, C>>>(bn1_g, bn1_b);
    gcn_kernel<<<dim3(8, B), 256>>>(gcn_w1, 0);
    gcn_kernel<<<dim3(8, B), 256>>>(gcn_w2, 1);
    conv_kernel<<<dim3(16, B), 128>>>(conv2_w, 1);
    bn2_partial_kernel<<<B, 256>>>();
    bn2_final_kernel<<<1, C>>>(bn2_g, bn2_b);
    final_kernel<<<dim3(NN / 64, C / 64, B), 256>>>(x, out);
}